// round 15
// baseline (speedup 1.0000x reference)
#include <cuda_runtime.h>
#include <math.h>
#include <stdint.h>

#define N_ROWS 8192
#define DIM    128

#define NT 56            // rows per block -> 147 blocks (one per SM)
#define KC 32            // i-chunk
#define NCH (DIM / KC)   // 4 chunks
#define THREADS 512      // 32 col-threads x 16 warps
#define OR 4             // cols per thread (full o = 128)
#define XSTR 36          // padded float stride for raw x rows
#define NBLOCKS ((N_ROWS + NT - 1) / NT)   // 147

// ---- smem layout ----
// compute-facing planes (single buffer, rebuilt per chunk):
#define SG_OFF     0                              // g     [KC][DIM] f32  16KB
#define SWYZ_OFF   (KC * DIM * 4)                 // wyz   [KC][DIM] f32x2 32KB
#define SPQ_OFF    (SWYZ_OFF + KC * DIM * 8)      // pq    [KC][DIM] f32x2 32KB
#define PLANES_BYTES (SPQ_OFF + KC * DIM * 8)     // 81920
// raw double-buffered stages:
#define RWR_OFF    0
#define RWI_OFF    (KC * DIM * 4)                 // 16384
#define RG_OFF     (RWI_OFF + KC * DIM * 4)       // 32768
#define RX_OFF     (RG_OFF + KC * DIM * 4)        // 49152
#define RAW_BYTES  ((RX_OFF + NT * XSTR * 4 + 127) & ~127)   // 57344
#define RAW0_OFF   PLANES_BYTES
#define SMEM_TOTAL (PLANES_BYTES + 2 * RAW_BYTES) // 196608

#define FMA_F32X2(d, a, b) \
    asm("fma.rn.f32x2 %0, %1, %2, %0;" : "+l"(d) : "l"(a), "l"(b))
#define PACK_DUP(d, s) \
    asm("mov.b64 %0, {%1, %1};" : "=l"(d) : "r"(s))

__device__ __forceinline__ void cp16(uint32_t dst, const void* src) {
    asm volatile("cp.async.cg.shared.global [%0], [%1], 16;"
                 :: "r"(dst), "l"(src));
}

// Stage raw Wr/Wi/G chunk + raw x chunk via cp.async.
__device__ __forceinline__ void stage_raw(const float* __restrict__ Wr,
                                          const float* __restrict__ Wi,
                                          const float* __restrict__ G,
                                          const float* __restrict__ x,
                                          int i0, uint32_t st,
                                          int n0, int tid) {
    #pragma unroll
    for (int k = tid; k < KC * DIM / 4; k += THREADS) {   // 1024 cp16 per plane
        int ir = k >> 5, o4 = (k & 31) * 4;
        uint32_t off = (uint32_t)(ir * DIM + o4) * 4;
        int src = (i0 + ir) * DIM + o4;
        cp16(st + RWR_OFF + off, &Wr[src]);
        cp16(st + RWI_OFF + off, &Wi[src]);
        cp16(st + RG_OFF  + off, &G [src]);
    }
    if (tid < NT * KC / 4) {                              // x: 448 cp16
        int n  = tid >> 3;            // 0..55
        int s4 = (tid & 7) * 4;       // 0..28
        int ng = n0 + n;
        if (ng >= N_ROWS) ng = N_ROWS - 1;   // clamp (stores guarded later)
        cp16(st + RX_OFF + (uint32_t)(n * XSTR + s4) * 4,
             &x[ng * DIM + i0 + s4]);
    }
}

// Transform raw weights -> packed planes (in-kernel prep).
__device__ __forceinline__ void xform_weights(const char* __restrict__ raw,
                                              char* __restrict__ planes,
                                              int tid) {
    const float* rWr = (const float*)(raw + RWR_OFF);
    const float* rWi = (const float*)(raw + RWI_OFF);
    const float* rG  = (const float*)(raw + RG_OFF);
    float*  sG   = (float*) (planes + SG_OFF);
    float2* sWyz = (float2*)(planes + SWYZ_OFF);
    float2* sPQ  = (float2*)(planes + SPQ_OFF);
    const float LN2 = 0.69314718055994530942f;
    const float PI  = 3.14159265358979323846f;
    #pragma unroll
    for (int k = tid; k < KC * DIM; k += THREADS) {       // 8 elems/thread
        float g = fminf(fmaxf(rG[k], 0.0f), 1.0f);
        float wr = rWr[k];
        float wi = rWi[k];
        sG[k]   = g;
        sWyz[k] = make_float2(LN2 * wr, LN2 * wi);
        sPQ[k]  = make_float2(-PI * g * wi, PI * g * wr);
    }
}

// Hot loop over one KC-chunk for NRA rows (R11 codegen, unchanged).
template<int NRA>
__device__ __forceinline__ void hot_chunk(const float* __restrict__ sG,
                                          const float2* __restrict__ sWyz,
                                          const float2* __restrict__ sPQ,
                                          const float* __restrict__ sX,
                                          int oc, int w,
                                          unsigned long long (&AB)[4][OR]) {
    #pragma unroll 2
    for (int i = 0; i < KC; i++) {
        float4 gv = *(const float4*)&sG[i * DIM + oc];
        ulonglong2 w01 = *(const ulonglong2*)&sWyz[i * DIM + oc];
        ulonglong2 w23 = *(const ulonglong2*)&sWyz[i * DIM + oc + 2];
        ulonglong2 p01 = *(const ulonglong2*)&sPQ [i * DIM + oc];
        ulonglong2 p23 = *(const ulonglong2*)&sPQ [i * DIM + oc + 2];
        unsigned long long wj[OR] = {w01.x, w01.y, w23.x, w23.y};
        unsigned long long pj[OR] = {p01.x, p01.y, p23.x, p23.y};
        float gj[OR] = {gv.x, gv.y, gv.z, gv.w};

        float am1[NRA];
        unsigned long long nfnf[NRA];
        #pragma unroll
        for (int r = 0; r < NRA; r++) {
            float xr = sX[(w + 16 * r) * XSTR + i];      // warp-broadcast
            am1[r] = (fabsf(xr) + 1e-36f) - 1.0f;
            float nf = xr < 0.0f ? 1.0f : 0.0f;
            PACK_DUP(nfnf[r], __float_as_uint(nf));
        }

        #pragma unroll
        for (int r = 0; r < NRA; r++) {
            #pragma unroll
            for (int j = 0; j < OR; j++) {
                float R = fmaf(am1[r], gj[j], 1.0f);     // a*g + (1-g)
                float t = __log2f(R);                     // MUFU.LG2
                unsigned long long tt;
                PACK_DUP(tt, __float_as_uint(t));
                FMA_F32X2(AB[r][j], tt, wj[j]);           // (A,B) += t*(wy,wz)
                FMA_F32X2(AB[r][j], nfnf[r], pj[j]);      // (A,B) += nf*(P,Q)
            }
        }
    }
}

__global__ __launch_bounds__(THREADS, 1)
void NPU_main_kernel(const float* __restrict__ x,
                     const float* __restrict__ Wr,
                     const float* __restrict__ Wi,
                     const float* __restrict__ G,
                     float* __restrict__ out) {
    extern __shared__ char smem[];
    const uint32_t sbase = (uint32_t)__cvta_generic_to_shared(smem);

    const int tid = threadIdx.x;
    const int n0  = blockIdx.x * NT;
    const int oc  = (tid & 31) * OR;     // col offset (0..124)
    const int w   = tid >> 5;            // warp id = row-group (0..15)
    const bool four_rows = (w < 8);      // warps 0-7: rows w+16r, r<4; else r<3

    unsigned long long AB[4][OR];
    #pragma unroll
    for (int r = 0; r < 4; r++)
        #pragma unroll
        for (int j = 0; j < OR; j++) AB[r][j] = 0ULL;

    stage_raw(Wr, Wi, G, x, 0, sbase + RAW0_OFF, n0, tid);
    asm volatile("cp.async.commit_group;");

    for (int c = 0; c < NCH; c++) {
        const int s = c & 1;
        if (c + 1 < NCH) {
            stage_raw(Wr, Wi, G, x, (c + 1) * KC,
                      sbase + RAW0_OFF + (uint32_t)((s ^ 1) * RAW_BYTES),
                      n0, tid);
            asm volatile("cp.async.commit_group;");
            asm volatile("cp.async.wait_group 1;");
        } else {
            asm volatile("cp.async.wait_group 0;");
        }
        __syncthreads();                 // raw(c) visible; planes free (hot c-1 done)

        const char* raw = smem + RAW0_OFF + s * RAW_BYTES;
        xform_weights(raw, smem, tid);
        __syncthreads();                 // planes(c) ready

        const float*  sG   = (const float*) (smem + SG_OFF);
        const float2* sWyz = (const float2*)(smem + SWYZ_OFF);
        const float2* sPQ  = (const float2*)(smem + SPQ_OFF);
        const float*  sX   = (const float*) (raw + RX_OFF);

        if (four_rows) hot_chunk<4>(sG, sWyz, sPQ, sX, oc, w, AB);
        else           hot_chunk<3>(sG, sWyz, sPQ, sX, oc, w, AB);

        __syncthreads();                 // raw(c)+planes consumed
    }

    // ---- epilogue: out = exp(A) * cos(B) (fast MUFU paths) ----
    const int nra = four_rows ? 4 : 3;
    #pragma unroll
    for (int r = 0; r < 4; r++) {
        if (r >= nra) break;
        int ng = n0 + w + 16 * r;
        if (ng >= N_ROWS) continue;
        float av[OR], bv[OR];
        #pragma unroll
        for (int j = 0; j < OR; j++) {
            av[j] = __uint_as_float((unsigned int)(AB[r][j] & 0xffffffffULL));
            bv[j] = __uint_as_float((unsigned int)(AB[r][j] >> 32));
        }
        float4 v;
        v.x = __expf(av[0]) * __cosf(bv[0]);
        v.y = __expf(av[1]) * __cosf(bv[1]);
        v.z = __expf(av[2]) * __cosf(bv[2]);
        v.w = __expf(av[3]) * __cosf(bv[3]);
        *(float4*)&out[ng * DIM + oc] = v;
    }
}

extern "C" void kernel_launch(void* const* d_in, const int* in_sizes, int n_in,
                              void* d_out, int out_size) {
    const float* x  = (const float*)d_in[0];
    const float* Wr = (const float*)d_in[1];
    const float* Wi = (const float*)d_in[2];
    const float* G  = (const float*)d_in[3];
    float* out = (float*)d_out;
    (void)in_sizes; (void)n_in; (void)out_size;

    cudaFuncSetAttribute(NPU_main_kernel,
                         cudaFuncAttributeMaxDynamicSharedMemorySize, SMEM_TOTAL);
    NPU_main_kernel<<<NBLOCKS, THREADS, SMEM_TOTAL>>>(x, Wr, Wi, G, out);
}

// round 16
// speedup vs baseline: 1.0099x; 1.0099x over previous
#include <cuda_runtime.h>
#include <math.h>
#include <stdint.h>

#define N_ROWS 8192
#define DIM    128

#define NT 56            // rows per block -> 147 blocks (one per SM)
#define KC 32            // i-chunk staged in smem
#define NCH (DIM / KC)   // 4 chunks
#define THREADS 512      // 32 col-threads x 16 warps
#define OR 4             // cols per thread (full o = 128)
#define NRW 7            // rows per warp (56 / 8 row-groups)
#define IH 16            // i-steps per warp per chunk (KC/2)
#define XSTR 36          // padded float stride for raw x rows
#define NBLOCKS ((N_ROWS + NT - 1) / NT)   // 147

// ---- packed weights (prep kernel output) ----
__device__ float  gG  [DIM * DIM];
__device__ float2 gWyz[DIM * DIM];   // (ln2*Wr, ln2*Wi)
__device__ float2 gPQ [DIM * DIM];   // (-pi*g*Wi, pi*g*Wr)

__global__ void NPU_prep_kernel(const float* __restrict__ Wr,
                                const float* __restrict__ Wi,
                                const float* __restrict__ G) {
    int idx = blockIdx.x * blockDim.x + threadIdx.x;
    if (idx >= DIM * DIM) return;
    float g = fminf(fmaxf(G[idx], 0.0f), 1.0f);
    float wr = Wr[idx];
    float wi = Wi[idx];
    const float LN2 = 0.69314718055994530942f;
    const float PI  = 3.14159265358979323846f;
    gG[idx]   = g;
    gWyz[idx] = make_float2(LN2 * wr, LN2 * wi);
    gPQ[idx]  = make_float2(-PI * g * wi, PI * g * wr);
}

// ---- smem: two stages, each g + wyz + pq + raw x rows ----
#define SG_OFF    0
#define SWYZ_OFF  (KC * DIM * 4)                   // 16384
#define SPQ_OFF   (SWYZ_OFF + KC * DIM * 8)        // 49152
#define SX_OFF    (SPQ_OFF + KC * DIM * 8)         // 81920
#define STG_BYTES (((SX_OFF + NT * XSTR * 4) + 127) & ~127)   // 90112
#define SMEM_TOTAL (2 * STG_BYTES)                 // 180224
// reduction scratch (after final barrier, reuses stage 0): 8*7*4*32 u64 = 57344 B

#define FMA_F32X2(d, a, b) \
    asm("fma.rn.f32x2 %0, %1, %2, %0;" : "+l"(d) : "l"(a), "l"(b))
#define PACK_DUP(d, s) \
    asm("mov.b64 %0, {%1, %1};" : "=l"(d) : "r"(s))

__device__ __forceinline__ void cp16(uint32_t dst, const void* src) {
    asm volatile("cp.async.cg.shared.global [%0], [%1], 16;"
                 :: "r"(dst), "l"(src));
}

__device__ __forceinline__ void stage_chunk(const float* __restrict__ x,
                                            int i0, uint32_t st,
                                            int n0, int tid) {
    #pragma unroll
    for (int k = tid; k < KC * DIM / 4; k += THREADS) {   // g: 1024 cp16
        int ir = k >> 5, o4 = (k & 31) * 4;
        cp16(st + SG_OFF + (uint32_t)(ir * DIM + o4) * 4,
             &gG[(i0 + ir) * DIM + o4]);
    }
    #pragma unroll
    for (int k = tid; k < KC * DIM / 2; k += THREADS) {   // wyz,pq: 2048 each
        int ir = k >> 6, o2 = (k & 63) * 2;
        cp16(st + SWYZ_OFF + (uint32_t)(ir * DIM + o2) * 8,
             &gWyz[(i0 + ir) * DIM + o2]);
        cp16(st + SPQ_OFF + (uint32_t)(ir * DIM + o2) * 8,
             &gPQ[(i0 + ir) * DIM + o2]);
    }
    if (tid < NT * KC / 4) {                              // x: 448 cp16
        int n  = tid >> 3;            // 0..55
        int s4 = (tid & 7) * 4;       // 0..28
        int ng = n0 + n;
        if (ng >= N_ROWS) ng = N_ROWS - 1;   // clamp (stores guarded later)
        cp16(st + SX_OFF + (uint32_t)(n * XSTR + s4) * 4,
             &x[ng * DIM + i0 + s4]);
    }
}

__global__ __launch_bounds__(THREADS, 1)
void NPU_main_kernel(const float* __restrict__ x, float* __restrict__ out) {
    extern __shared__ char smem[];
    const uint32_t sbase = (uint32_t)__cvta_generic_to_shared(smem);

    const int tid  = threadIdx.x;
    const int lane = tid & 31;
    const int n0   = blockIdx.x * NT;
    const int oc   = lane * OR;          // col offset (0..124)
    const int w    = tid >> 5;           // warp id (0..15)
    const int rg   = w & 7;              // row group: rows rg*7 .. rg*7+6
    const int ih   = (w >> 3) * IH;      // i-half base within chunk
    const int rbase = rg * NRW;          // first row of this warp

    unsigned long long AB[NRW][OR];
    #pragma unroll
    for (int r = 0; r < NRW; r++)
        #pragma unroll
        for (int j = 0; j < OR; j++) AB[r][j] = 0ULL;

    stage_chunk(x, 0, sbase, n0, tid);
    asm volatile("cp.async.commit_group;");

    for (int c = 0; c < NCH; c++) {
        const int s = c & 1;
        if (c + 1 < NCH) {
            stage_chunk(x, (c + 1) * KC, sbase + (uint32_t)((s ^ 1) * STG_BYTES),
                        n0, tid);
            asm volatile("cp.async.commit_group;");
            asm volatile("cp.async.wait_group 1;");
        } else {
            asm volatile("cp.async.wait_group 0;");
        }
        __syncthreads();                 // chunk c visible

        const char* stg = smem + s * STG_BYTES;
        const float*  sG   = (const float*) (stg + SG_OFF);
        const float2* sWyz = (const float2*)(stg + SWYZ_OFF);
        const float2* sPQ  = (const float2*)(stg + SPQ_OFF);
        const float*  sX   = (const float*) (stg + SX_OFF);

        // ---- hot loop: this warp's 16 i-steps, 7 rows x 4 cols ----
        #pragma unroll 1
        for (int ii = 0; ii < IH; ii++) {
            const int i = ih + ii;
            float4 gv = *(const float4*)&sG[i * DIM + oc];
            ulonglong2 w01 = *(const ulonglong2*)&sWyz[i * DIM + oc];
            ulonglong2 w23 = *(const ulonglong2*)&sWyz[i * DIM + oc + 2];
            ulonglong2 p01 = *(const ulonglong2*)&sPQ [i * DIM + oc];
            ulonglong2 p23 = *(const ulonglong2*)&sPQ [i * DIM + oc + 2];
            unsigned long long wj[OR] = {w01.x, w01.y, w23.x, w23.y};
            unsigned long long pj[OR] = {p01.x, p01.y, p23.x, p23.y};
            float gj[OR] = {gv.x, gv.y, gv.z, gv.w};

            float am1[NRW];
            unsigned long long nfnf[NRW];
            #pragma unroll
            for (int r = 0; r < NRW; r++) {
                float xr = sX[(rbase + r) * XSTR + i];   // warp-broadcast
                am1[r] = (fabsf(xr) + 1e-36f) - 1.0f;
                float nf = xr < 0.0f ? 1.0f : 0.0f;
                PACK_DUP(nfnf[r], __float_as_uint(nf));
            }

            #pragma unroll
            for (int r = 0; r < NRW; r++) {
                #pragma unroll
                for (int j = 0; j < OR; j++) {
                    float R = fmaf(am1[r], gj[j], 1.0f); // a*g + (1-g)
                    float t = __log2f(R);                 // MUFU.LG2
                    unsigned long long tt;
                    PACK_DUP(tt, __float_as_uint(t));
                    FMA_F32X2(AB[r][j], tt, wj[j]);       // (A,B) += t*(wy,wz)
                    FMA_F32X2(AB[r][j], nfnf[r], pj[j]);  // (A,B) += nf*(P,Q)
                }
            }
        }
        __syncthreads();                 // chunk c consumed
    }

    // ---- cross-half reduction: upper warps (i 16..31) dump, lower add ----
    unsigned long long* red = (unsigned long long*)smem;   // stage 0, now free
    if (w >= 8) {
        #pragma unroll
        for (int r = 0; r < NRW; r++)
            #pragma unroll
            for (int j = 0; j < OR; j++)
                red[(((rg * NRW + r) * OR + j) << 5) + lane] = AB[r][j];
    }
    __syncthreads();

    if (w < 8) {
        const unsigned long long ONES2 = 0x3F8000003F800000ULL;  // (1.0f,1.0f)
        #pragma unroll
        for (int r = 0; r < NRW; r++)
            #pragma unroll
            for (int j = 0; j < OR; j++) {
                unsigned long long other =
                    red[(((rg * NRW + r) * OR + j) << 5) + lane];
                FMA_F32X2(AB[r][j], other, ONES2);        // packed add
            }

        // ---- epilogue: out = exp(A) * cos(B) (fast MUFU paths) ----
        #pragma unroll
        for (int r = 0; r < NRW; r++) {
            int ng = n0 + rbase + r;
            if (ng >= N_ROWS) continue;
            float av[OR], bv[OR];
            #pragma unroll
            for (int j = 0; j < OR; j++) {
                av[j] = __uint_as_float((unsigned int)(AB[r][j] & 0xffffffffULL));
                bv[j] = __uint_as_float((unsigned int)(AB[r][j] >> 32));
            }
            float4 v;
            v.x = __expf(av[0]) * __cosf(bv[0]);
            v.y = __expf(av[1]) * __cosf(bv[1]);
            v.z = __expf(av[2]) * __cosf(bv[2]);
            v.w = __expf(av[3]) * __cosf(bv[3]);
            *(float4*)&out[ng * DIM + oc] = v;
        }
    }
}

extern "C" void kernel_launch(void* const* d_in, const int* in_sizes, int n_in,
                              void* d_out, int out_size) {
    const float* x  = (const float*)d_in[0];
    const float* Wr = (const float*)d_in[1];
    const float* Wi = (const float*)d_in[2];
    const float* G  = (const float*)d_in[3];
    float* out = (float*)d_out;
    (void)in_sizes; (void)n_in; (void)out_size;

    NPU_prep_kernel<<<(DIM * DIM + 255) / 256, 256>>>(Wr, Wi, G);

    cudaFuncSetAttribute(NPU_main_kernel,
                         cudaFuncAttributeMaxDynamicSharedMemorySize, SMEM_TOTAL);
    NPU_main_kernel<<<NBLOCKS, THREADS, SMEM_TOTAL>>>(x, out);
}